// round 2
// baseline (speedup 1.0000x reference)
#include <cuda_runtime.h>
#include <cuda_bf16.h>

// Problem: B=32, T=32, L=196, S=512, D=512
// Inputs: 0:x[32,32,512] 1:x_static[32,196,512] 2:h0 3:W1[512,512] 4:W2 5:W3[1024,512]
//         6:b2 7:b3[512] 8:V[512,1]
// Math reduction: softmax is shift-invariant => attention weights do NOT depend on h.
//   attn[b,:]  = softmax_l( x_static[b] @ (W1@V) )
//   ctx[b,:]   = attn[b,:] @ x_static[b]                       (constant over t)
//   c[b,:]     = ctx[b,:] @ W3[512:,:] + b3
//   out[b,t,:] = x[b,t,:] @ W3[:512,:] + c[b,:]

#define D_ 512
#define S_ 512
#define L_ 196
#define B_ 32
#define T_ 32

__device__ float g_w1v[S_];        // W1 @ V
__device__ float g_c[B_ * D_];     // per-batch constant bias

// ---------------------------------------------------------------------------
// Kernel A: w1v[s] = dot(W1[s,:], V)
// ---------------------------------------------------------------------------
__global__ __launch_bounds__(256) void w1v_kernel(const float* __restrict__ W1,
                                                  const float* __restrict__ V) {
    int gwarp = (blockIdx.x * blockDim.x + threadIdx.x) >> 5;
    int lane = threadIdx.x & 31;
    int nwarps = (gridDim.x * blockDim.x) >> 5;
    for (int s = gwarp; s < S_; s += nwarps) {
        const float* row = W1 + s * D_;
        float acc = 0.0f;
#pragma unroll 4
        for (int d = lane; d < D_; d += 32) acc += row[d] * V[d];
#pragma unroll
        for (int o = 16; o; o >>= 1) acc += __shfl_xor_sync(0xffffffffu, acc, o);
        if (lane == 0) g_w1v[s] = acc;
    }
}

// ---------------------------------------------------------------------------
// Kernel B: per-batch scores -> softmax -> ctx -> c = ctx@W3bot + b3
// One block per batch (32 blocks, 256 threads).
// ---------------------------------------------------------------------------
__global__ __launch_bounds__(256) void attn_ctx_kernel(const float* __restrict__ xs,
                                                       const float* __restrict__ W3,
                                                       const float* __restrict__ b3) {
    int b = blockIdx.x;
    const float* X = xs + (size_t)b * L_ * S_;
    __shared__ float sc[L_];
    __shared__ float ctx[S_];
    __shared__ float red[8];
    __shared__ float s_max, s_sum;

    int tid = threadIdx.x;
    int warp = tid >> 5, lane = tid & 31;

    // pass 1: scores[l] = dot(X[l,:], w1v)
    for (int l = warp; l < L_; l += 8) {
        const float* row = X + l * S_;
        float acc = 0.0f;
#pragma unroll 4
        for (int s = lane; s < S_; s += 32) acc += row[s] * g_w1v[s];
#pragma unroll
        for (int o = 16; o; o >>= 1) acc += __shfl_xor_sync(0xffffffffu, acc, o);
        if (lane == 0) sc[l] = acc;
    }
    __syncthreads();

    // softmax max
    float m = -1e30f;
    for (int l = tid; l < L_; l += 256) m = fmaxf(m, sc[l]);
#pragma unroll
    for (int o = 16; o; o >>= 1) m = fmaxf(m, __shfl_xor_sync(0xffffffffu, m, o));
    if (lane == 0) red[warp] = m;
    __syncthreads();
    if (warp == 0) {
        float v = (lane < 8) ? red[lane] : -1e30f;
#pragma unroll
        for (int o = 4; o; o >>= 1) v = fmaxf(v, __shfl_xor_sync(0xffffffffu, v, o));
        if (lane == 0) s_max = v;
    }
    __syncthreads();
    float mx = s_max;

    // exp + sum
    float psum = 0.0f;
    for (int l = tid; l < L_; l += 256) {
        float e = __expf(sc[l] - mx);
        sc[l] = e;
        psum += e;
    }
#pragma unroll
    for (int o = 16; o; o >>= 1) psum += __shfl_xor_sync(0xffffffffu, psum, o);
    if (lane == 0) red[warp] = psum;
    __syncthreads();
    if (warp == 0) {
        float v = (lane < 8) ? red[lane] : 0.0f;
#pragma unroll
        for (int o = 4; o; o >>= 1) v += __shfl_xor_sync(0xffffffffu, v, o);
        if (lane == 0) s_sum = v;
    }
    __syncthreads();
    float inv = 1.0f / s_sum;

    // pass 2: ctx[s] = sum_l attn[l] * X[l,s]  (two accumulators per thread)
    {
        float a0 = 0.0f, a1 = 0.0f;
        const float* X0 = X + tid;
        const float* X1 = X + tid + 256;
#pragma unroll 4
        for (int l = 0; l < L_; l++) {
            float w = sc[l];
            a0 += w * X0[l * S_];
            a1 += w * X1[l * S_];
        }
        ctx[tid] = a0 * inv;
        ctx[tid + 256] = a1 * inv;
    }
    __syncthreads();

    // pass 3: c[d] = b3[d] + sum_s ctx[s] * W3[512+s, d]
    {
        float a0 = b3[tid], a1 = b3[tid + 256];
        const float* Wb = W3 + (size_t)S_ * D_;  // bottom half of W3
#pragma unroll 4
        for (int s = 0; s < S_; s++) {
            float w = ctx[s];
            const float* row = Wb + s * D_;
            a0 += w * row[tid];
            a1 += w * row[tid + 256];
        }
        g_c[b * D_ + tid] = a0;
        g_c[b * D_ + tid + 256] = a1;
    }
}

// ---------------------------------------------------------------------------
// Kernel D: out[m,n] = sum_k x[m,k] * W3[k,n] + c[m>>5, n]
// M=1024, N=512, K=512.  BM=BN=64, BK=32, 16x16 threads, 4x4 microtile.
// Vectorized float4 tile loads (all base pointers / strides are 16B-aligned).
// ---------------------------------------------------------------------------
#define BM 64
#define BN 64
#define BK 32
#define TM 4
#define TN 4

__global__ __launch_bounds__(256) void out_gemm(const float* __restrict__ A,
                                                const float* __restrict__ W3,
                                                float* __restrict__ out) {
    __shared__ float As[BK][BM + 4];
    __shared__ float Bs[BK][BN + 4];

    int tid = threadIdx.x;
    int tx = tid & 15, ty = tid >> 4;
    int m0 = blockIdx.y * BM, n0 = blockIdx.x * BN;

    float acc[TM][TN];
#pragma unroll
    for (int i = 0; i < TM; i++)
#pragma unroll
        for (int j = 0; j < TN; j++) acc[i][j] = 0.0f;

    // A-tile load mapping: 64 rows x 32 cols (8 float4 per row), 256 threads
    // -> each thread loads 2 float4. thread t handles row = t/4 (+32), col4 = t%4 *? ...
    // Simpler: linear over 64*8=512 float4 slots, 256 threads -> 2 iterations.
    // B-tile: 32 rows x 64 cols = 32*16=512 float4 slots -> 2 iterations.
    for (int k0 = 0; k0 < D_; k0 += BK) {
        // load A tile 64x32 as float4, store transposed As[k][m]
#pragma unroll
        for (int it = 0; it < 2; it++) {
            int slot = tid + it * 256;      // 0..511
            int m = slot >> 3;              // /8  (8 float4 per row)
            int k4 = slot & 7;              // float4 index within row
            float4 v = *(const float4*)(A + (size_t)(m0 + m) * D_ + k0 + k4 * 4);
            As[k4 * 4 + 0][m] = v.x;
            As[k4 * 4 + 1][m] = v.y;
            As[k4 * 4 + 2][m] = v.z;
            As[k4 * 4 + 3][m] = v.w;
        }
        // load B tile 32x64 as float4
#pragma unroll
        for (int it = 0; it < 2; it++) {
            int slot = tid + it * 256;      // 0..511
            int k = slot >> 4;              // /16 (16 float4 per row)
            int n4 = slot & 15;
            float4 v = *(const float4*)(W3 + (size_t)(k0 + k) * D_ + n0 + n4 * 4);
            *(float4*)&Bs[k][n4 * 4] = v;
        }
        __syncthreads();

#pragma unroll
        for (int k = 0; k < BK; k++) {
            float a[TM], bb[TN];
#pragma unroll
            for (int i = 0; i < TM; i++) a[i] = As[k][ty * TM + i];
#pragma unroll
            for (int j = 0; j < TN; j++) bb[j] = Bs[k][tx * TN + j];
#pragma unroll
            for (int i = 0; i < TM; i++)
#pragma unroll
                for (int j = 0; j < TN; j++) acc[i][j] += a[i] * bb[j];
        }
        __syncthreads();
    }

#pragma unroll
    for (int i = 0; i < TM; i++) {
        int m = m0 + ty * TM + i;
        int bidx = m >> 5;  // m / T_
        const float* crow = g_c + bidx * D_;
        int n = n0 + tx * TN;
        float4 cv = *(const float4*)(crow + n);
        float4 ov;
        ov.x = acc[i][0] + cv.x;
        ov.y = acc[i][1] + cv.y;
        ov.z = acc[i][2] + cv.z;
        ov.w = acc[i][3] + cv.w;
        *(float4*)(out + (size_t)m * D_ + n) = ov;
    }
}

extern "C" void kernel_launch(void* const* d_in, const int* in_sizes, int n_in,
                              void* d_out, int out_size) {
    const float* x  = (const float*)d_in[0];   // [32,32,512]
    const float* xs = (const float*)d_in[1];   // [32,196,512]
    const float* W1 = (const float*)d_in[3];   // [512,512]
    const float* W3 = (const float*)d_in[5];   // [1024,512]
    const float* b3 = (const float*)d_in[7];   // [512]
    const float* V  = (const float*)d_in[8];   // [512,1]
    float* out = (float*)d_out;                // [32,32,512]

    w1v_kernel<<<16, 256>>>(W1, V);
    attn_ctx_kernel<<<B_, 256>>>(xs, W3, b3);
    out_gemm<<<dim3(D_ / BN, (B_ * T_) / BM), 256>>>(x, W3, out);
}

// round 3
// speedup vs baseline: 1.0184x; 1.0184x over previous
#include <cuda_runtime.h>
#include <cuda_bf16.h>

// Problem: B=32, T=32, L=196, S=512, D=512
// Math reduction: softmax is shift-invariant => attention independent of h,t.
//   attn[b,:]  = softmax_l( x_static[b] @ (W1@V) )
//   ctx[b,:]   = attn[b,:] @ x_static[b]
//   c[b,:]     = ctx[b,:] @ W3[512:,:] + b3
//   out[b,t,:] = x[b,t,:] @ W3[:512,:] + c[b,:]

#define D_ 512
#define S_ 512
#define L_ 196
#define B_ 32
#define T_ 32

__device__ float g_w1v[S_];
__device__ float g_ctx[B_ * S_];
__device__ float g_c[B_ * D_];

// ---------------------------------------------------------------------------
// Kernel 1: w1v[s] = dot(W1[s,:], V). 128 CTAs, warp per row, float4.
// ---------------------------------------------------------------------------
__global__ __launch_bounds__(256) void w1v_kernel(const float* __restrict__ W1,
                                                  const float* __restrict__ V) {
    int gwarp = (blockIdx.x * blockDim.x + threadIdx.x) >> 5;
    int lane = threadIdx.x & 31;
    if (gwarp >= S_) return;
    const float4* row = (const float4*)(W1 + (size_t)gwarp * D_);
    const float4* v4 = (const float4*)V;
    float acc = 0.0f;
#pragma unroll
    for (int i = 0; i < 4; i++) {
        int idx = lane + i * 32;  // 128 float4 per row
        float4 a = row[idx];
        float4 b = v4[idx];
        acc += a.x * b.x + a.y * b.y + a.z * b.z + a.w * b.w;
    }
#pragma unroll
    for (int o = 16; o; o >>= 1) acc += __shfl_xor_sync(0xffffffffu, acc, o);
    if (lane == 0) g_w1v[gwarp] = acc;
}

// ---------------------------------------------------------------------------
// Kernel 2: per-batch scores -> softmax -> ctx. 32 blocks x 1024 threads.
// ---------------------------------------------------------------------------
__global__ __launch_bounds__(1024) void attn_ctx_kernel(const float* __restrict__ xs) {
    int b = blockIdx.x;
    const float* X = xs + (size_t)b * L_ * S_;
    __shared__ float sw1v[S_];
    __shared__ float sc[L_];
    __shared__ float ctx2[2][S_];
    __shared__ float red[32];
    __shared__ float s_max, s_sum;

    int tid = threadIdx.x;
    int warp = tid >> 5, lane = tid & 31;

    // cache w1v in smem
    if (tid < S_ / 4) ((float4*)sw1v)[tid] = ((const float4*)g_w1v)[tid];
    __syncthreads();

    // pass 1: scores[l] = dot(X[l,:], w1v), warp per row, float4
    for (int l = warp; l < L_; l += 32) {
        const float4* row = (const float4*)(X + (size_t)l * S_);
        const float4* w4 = (const float4*)sw1v;
        float acc = 0.0f;
#pragma unroll
        for (int i = 0; i < 4; i++) {
            int idx = lane + i * 32;
            float4 a = row[idx];
            float4 w = w4[idx];
            acc += a.x * w.x + a.y * w.y + a.z * w.z + a.w * w.w;
        }
#pragma unroll
        for (int o = 16; o; o >>= 1) acc += __shfl_xor_sync(0xffffffffu, acc, o);
        if (lane == 0) sc[l] = acc;
    }
    __syncthreads();

    // block-wide softmax max over L_=196
    float m = (tid < L_) ? sc[tid] : -1e30f;
#pragma unroll
    for (int o = 16; o; o >>= 1) m = fmaxf(m, __shfl_xor_sync(0xffffffffu, m, o));
    if (lane == 0) red[warp] = m;
    __syncthreads();
    if (warp == 0) {
        float v = red[lane];
#pragma unroll
        for (int o = 16; o; o >>= 1) v = fmaxf(v, __shfl_xor_sync(0xffffffffu, v, o));
        if (lane == 0) s_max = v;
    }
    __syncthreads();
    float mx = s_max;

    float e = (tid < L_) ? __expf(sc[tid] - mx) : 0.0f;
    if (tid < L_) sc[tid] = e;
    float ps = e;
#pragma unroll
    for (int o = 16; o; o >>= 1) ps += __shfl_xor_sync(0xffffffffu, ps, o);
    if (lane == 0) red[warp] = ps;
    __syncthreads();
    if (warp == 0) {
        float v = red[lane];
#pragma unroll
        for (int o = 16; o; o >>= 1) v += __shfl_xor_sync(0xffffffffu, v, o);
        if (lane == 0) s_sum = v;
    }
    __syncthreads();
    float inv = 1.0f / s_sum;

    // pass 2: ctx[s] = sum_l attn[l] * X[l,s], split l into 2 halves across threads
    {
        int s = tid & (S_ - 1);
        int half = tid >> 9;           // 0 or 1
        int l0 = half * (L_ / 2);      // 0 or 98
        float acc = 0.0f;
        const float* Xp = X + s + (size_t)l0 * S_;
#pragma unroll 7
        for (int l = 0; l < L_ / 2; l++) {
            acc += sc[l0 + l] * Xp[(size_t)l * S_];
        }
        ctx2[half][s] = acc;
    }
    __syncthreads();
    if (tid < S_) {
        g_ctx[b * S_ + tid] = (ctx2[0][tid] + ctx2[1][tid]) * inv;
    }
}

// ---------------------------------------------------------------------------
// Kernel 3: c[b,d] = b3[d] + sum_s ctx[b,s] * W3bot[s,d]
// grid 8 (d-chunks of 64), 256 threads: 16 groups x (2 b's x 4 d's).
// ---------------------------------------------------------------------------
#define CKT 128
__global__ __launch_bounds__(256) void c_gemm(const float* __restrict__ W3,
                                              const float* __restrict__ b3) {
    __shared__ float sctx[B_][CKT];
    const float* Wb = W3 + (size_t)S_ * D_;
    int tid = threadIdx.x;
    int d4 = tid & 15;                 // float4 index within 64-wide chunk
    int grp = tid >> 4;                // 0..15
    int chunk = blockIdx.x * 64;
    int d = chunk + d4 * 4;

    float acc[2][4];
#pragma unroll
    for (int i = 0; i < 2; i++)
#pragma unroll
        for (int j = 0; j < 4; j++) acc[i][j] = 0.0f;

    for (int kt = 0; kt < S_; kt += CKT) {
        // load ctx tile [32][128] = 4096 floats, 256 threads -> 4 float4 each
#pragma unroll
        for (int it = 0; it < 4; it++) {
            int slot = tid + it * 256;     // 0..1023 float4 slots
            int bb = slot >> 5;            // /32 (32 float4 per row)
            int kk = slot & 31;
            float4 v = ((const float4*)(g_ctx + bb * S_ + kt))[kk];
            *(float4*)&sctx[bb][kk * 4] = v;
        }
        __syncthreads();
#pragma unroll 4
        for (int k = 0; k < CKT; k++) {
            float4 w = *(const float4*)(Wb + (size_t)(kt + k) * D_ + d);
            float c0 = sctx[grp * 2 + 0][k];
            float c1 = sctx[grp * 2 + 1][k];
            acc[0][0] += c0 * w.x; acc[0][1] += c0 * w.y;
            acc[0][2] += c0 * w.z; acc[0][3] += c0 * w.w;
            acc[1][0] += c1 * w.x; acc[1][1] += c1 * w.y;
            acc[1][2] += c1 * w.z; acc[1][3] += c1 * w.w;
        }
        __syncthreads();
    }

    float4 bias = *(const float4*)(b3 + d);
#pragma unroll
    for (int i = 0; i < 2; i++) {
        int b = grp * 2 + i;
        float4 o;
        o.x = acc[i][0] + bias.x;
        o.y = acc[i][1] + bias.y;
        o.z = acc[i][2] + bias.z;
        o.w = acc[i][3] + bias.w;
        *(float4*)(g_c + b * D_ + d) = o;
    }
}

// ---------------------------------------------------------------------------
// Kernel 4: out[m,n] = sum_k x[m,k] * W3top[k,n] + c[m>>5, n]
// M=1024, N=512, K=512. BM=BN=64, BK=32, 256 threads, 4x4 microtile.
// float4 global loads, float4 shared reads.
// ---------------------------------------------------------------------------
#define BM 64
#define BN 64
#define BK 32
#define TM 4
#define TN 4

__global__ __launch_bounds__(256) void out_gemm(const float* __restrict__ A,
                                                const float* __restrict__ W3,
                                                float* __restrict__ out) {
    __shared__ float As[BK][BM + 4];
    __shared__ float Bs[BK][BN + 4];

    int tid = threadIdx.x;
    int tx = tid & 15, ty = tid >> 4;
    int m0 = blockIdx.y * BM, n0 = blockIdx.x * BN;

    float acc[TM][TN];
#pragma unroll
    for (int i = 0; i < TM; i++)
#pragma unroll
        for (int j = 0; j < TN; j++) acc[i][j] = 0.0f;

    for (int k0 = 0; k0 < D_; k0 += BK) {
#pragma unroll
        for (int it = 0; it < 2; it++) {
            int slot = tid + it * 256;      // 64 rows x 8 float4
            int m = slot >> 3;
            int k4 = slot & 7;
            float4 v = *(const float4*)(A + (size_t)(m0 + m) * D_ + k0 + k4 * 4);
            As[k4 * 4 + 0][m] = v.x;
            As[k4 * 4 + 1][m] = v.y;
            As[k4 * 4 + 2][m] = v.z;
            As[k4 * 4 + 3][m] = v.w;
        }
#pragma unroll
        for (int it = 0; it < 2; it++) {
            int slot = tid + it * 256;      // 32 rows x 16 float4
            int k = slot >> 4;
            int n4 = slot & 15;
            float4 v = *(const float4*)(W3 + (size_t)(k0 + k) * D_ + n0 + n4 * 4);
            *(float4*)&Bs[k][n4 * 4] = v;
        }
        __syncthreads();

#pragma unroll
        for (int k = 0; k < BK; k++) {
            float4 a4 = *(const float4*)&As[k][ty * TM];
            float4 b4 = *(const float4*)&Bs[k][tx * TN];
            float a[TM] = {a4.x, a4.y, a4.z, a4.w};
            float bb[TN] = {b4.x, b4.y, b4.z, b4.w};
#pragma unroll
            for (int i = 0; i < TM; i++)
#pragma unroll
                for (int j = 0; j < TN; j++) acc[i][j] += a[i] * bb[j];
        }
        __syncthreads();
    }

#pragma unroll
    for (int i = 0; i < TM; i++) {
        int m = m0 + ty * TM + i;
        const float* crow = g_c + (m >> 5) * D_;
        int n = n0 + tx * TN;
        float4 cv = *(const float4*)(crow + n);
        float4 ov;
        ov.x = acc[i][0] + cv.x;
        ov.y = acc[i][1] + cv.y;
        ov.z = acc[i][2] + cv.z;
        ov.w = acc[i][3] + cv.w;
        *(float4*)(out + (size_t)m * D_ + n) = ov;
    }
}

extern "C" void kernel_launch(void* const* d_in, const int* in_sizes, int n_in,
                              void* d_out, int out_size) {
    const float* x  = (const float*)d_in[0];   // [32,32,512]
    const float* xs = (const float*)d_in[1];   // [32,196,512]
    const float* W1 = (const float*)d_in[3];   // [512,512]
    const float* W3 = (const float*)d_in[5];   // [1024,512]
    const float* b3 = (const float*)d_in[7];   // [512]
    const float* V  = (const float*)d_in[8];   // [512,1]
    float* out = (float*)d_out;                // [32,32,512]

    w1v_kernel<<<64, 256>>>(W1, V);            // 512 warps, warp per row
    attn_ctx_kernel<<<B_, 1024>>>(xs);
    c_gemm<<<8, 256>>>(W3, b3);
    out_gemm<<<dim3(D_ / BN, (B_ * T_) / BM), 256>>>(x, W3, out);
}

// round 4
// speedup vs baseline: 2.2530x; 2.2123x over previous
#include <cuda_runtime.h>
#include <cuda_bf16.h>

// Problem: B=32, T=32, L=196, S=512, D=512
// Math reduction: softmax is shift-invariant => attention independent of h,t.
//   attn[b,:]  = softmax_l( x_static[b] @ (W1@V) )
//   ctx[b,:]   = attn[b,:] @ x_static[b]
//   c[b,:]     = ctx[b,:] @ W3[512:,:] + b3
//   out[b,t,:] = x[b,t,:] @ W3[:512,:] + c[b,:]

#define D_ 512
#define S_ 512
#define L_ 196
#define B_ 32
#define T_ 32

__device__ float g_w1v[S_];
__device__ float g_scores[B_ * L_];
__device__ float g_ctx[B_ * S_];
__device__ float g_c[B_ * D_];

// ---- packed fp32x2 helpers (Blackwell FFMA2, PTX-only) ----------------------
__device__ __forceinline__ unsigned long long pack2(float lo, float hi) {
    unsigned long long r;
    asm("mov.b64 %0, {%1, %2};" : "=l"(r) : "f"(lo), "f"(hi));
    return r;
}
__device__ __forceinline__ void fma2(unsigned long long& d, unsigned long long a,
                                     unsigned long long b) {
    asm("fma.rn.f32x2 %0, %1, %2, %0;" : "+l"(d) : "l"(a), "l"(b));
}
__device__ __forceinline__ float2 unpack2(unsigned long long p) {
    float2 f;
    asm("mov.b64 {%0, %1}, %2;" : "=f"(f.x), "=f"(f.y) : "l"(p));
    return f;
}

// ---------------------------------------------------------------------------
// Kernel 1: w1v[s] = dot(W1[s,:], V). warp per row, float4.
// ---------------------------------------------------------------------------
__global__ __launch_bounds__(256) void w1v_kernel(const float* __restrict__ W1,
                                                  const float* __restrict__ V) {
    int gwarp = (blockIdx.x * blockDim.x + threadIdx.x) >> 5;
    int lane = threadIdx.x & 31;
    if (gwarp >= S_) return;
    const float4* row = (const float4*)(W1 + (size_t)gwarp * D_);
    const float4* v4 = (const float4*)V;
    float acc = 0.0f;
#pragma unroll
    for (int i = 0; i < 4; i++) {
        int idx = lane + i * 32;
        float4 a = row[idx];
        float4 b = v4[idx];
        acc += a.x * b.x + a.y * b.y + a.z * b.z + a.w * b.w;
    }
#pragma unroll
    for (int o = 16; o; o >>= 1) acc += __shfl_xor_sync(0xffffffffu, acc, o);
    if (lane == 0) g_w1v[gwarp] = acc;
}

// ---------------------------------------------------------------------------
// Kernel 2: scores[b,l] = dot(x_static[b,l,:], w1v). grid (7, 32), warp/row.
// ---------------------------------------------------------------------------
__global__ __launch_bounds__(256) void scores_kernel(const float* __restrict__ xs) {
    int b = blockIdx.y;
    int l0 = blockIdx.x * 28;
    __shared__ float sw1v[S_];
    int tid = threadIdx.x;
    if (tid < S_ / 4) ((float4*)sw1v)[tid] = ((const float4*)g_w1v)[tid];
    __syncthreads();

    int warp = tid >> 5, lane = tid & 31;
    const float* X = xs + (size_t)b * L_ * S_;
    for (int r = warp; r < 28; r += 8) {
        int l = l0 + r;
        const float4* row = (const float4*)(X + (size_t)l * S_);
        const float4* w4 = (const float4*)sw1v;
        float acc = 0.0f;
#pragma unroll
        for (int i = 0; i < 4; i++) {
            int idx = lane + i * 32;
            float4 a = row[idx];
            float4 w = w4[idx];
            acc += a.x * w.x + a.y * w.y + a.z * w.z + a.w * w.w;
        }
#pragma unroll
        for (int o = 16; o; o >>= 1) acc += __shfl_xor_sync(0xffffffffu, acc, o);
        if (lane == 0) g_scores[b * L_ + l] = acc;
    }
}

// ---------------------------------------------------------------------------
// Kernel 3: softmax (recomputed per block) + ctx.
// grid (4, 32): s-chunk of 128, batch b. block 128.
// ---------------------------------------------------------------------------
__global__ __launch_bounds__(128) void ctx_kernel(const float* __restrict__ xs) {
    int b = blockIdx.y;
    int s = blockIdx.x * 128 + threadIdx.x;
    __shared__ float sc[L_];
    __shared__ float red[4];
    __shared__ float s_max, s_sum;
    int tid = threadIdx.x;
    int warp = tid >> 5, lane = tid & 31;

    // load scores
    float v0 = g_scores[b * L_ + tid];
    float v1 = (tid + 128 < L_) ? g_scores[b * L_ + tid + 128] : -1e30f;
    sc[tid] = v0;
    if (tid + 128 < L_) sc[tid + 128] = v1;

    // block max
    float m = fmaxf(v0, v1);
#pragma unroll
    for (int o = 16; o; o >>= 1) m = fmaxf(m, __shfl_xor_sync(0xffffffffu, m, o));
    if (lane == 0) red[warp] = m;
    __syncthreads();
    if (tid == 0) {
        s_max = fmaxf(fmaxf(red[0], red[1]), fmaxf(red[2], red[3]));
    }
    __syncthreads();
    float mx = s_max;

    // exp + sum
    float e0 = __expf(v0 - mx);
    float e1 = (tid + 128 < L_) ? __expf(v1 - mx) : 0.0f;
    float ps = e0 + e1;
#pragma unroll
    for (int o = 16; o; o >>= 1) ps += __shfl_xor_sync(0xffffffffu, ps, o);
    if (lane == 0) red[warp] = ps;
    __syncthreads();
    if (tid == 0) s_sum = red[0] + red[1] + red[2] + red[3];
    __syncthreads();
    float inv = 1.0f / s_sum;
    sc[tid] = e0 * inv;
    if (tid + 128 < L_) sc[tid + 128] = e1 * inv;
    __syncthreads();

    // ctx[s] = sum_l attn[l] * X[l,s]
    const float* Xp = xs + (size_t)b * L_ * S_ + s;
    float acc = 0.0f;
#pragma unroll 4
    for (int l = 0; l < L_; l++) acc += sc[l] * Xp[(size_t)l * S_];
    g_ctx[b * S_ + s] = acc;
}

// ---------------------------------------------------------------------------
// Kernel 4: c[b,d] = b3[d] + sum_s ctx[b,s] * W3bot[s,d]
// grid 16 (d-chunks of 32), block 256: thread = (b = tid>>3, dgrp = tid&7).
// ---------------------------------------------------------------------------
#define CKT 128
__global__ __launch_bounds__(256) void c_gemm(const float* __restrict__ W3,
                                              const float* __restrict__ b3) {
    __shared__ float sctx[B_][CKT + 4];
    __shared__ float sW[CKT][32];
    const float* Wb = W3 + (size_t)S_ * D_;
    int tid = threadIdx.x;
    int b = tid >> 3;
    int dgrp = tid & 7;
    int chunk = blockIdx.x * 32;
    int d = chunk + dgrp * 4;

    float acc[4] = {0.0f, 0.0f, 0.0f, 0.0f};

    for (int kt = 0; kt < S_; kt += CKT) {
        // sctx tile: 32 rows x 128 floats = 1024 float4, 4 per thread
#pragma unroll
        for (int it = 0; it < 4; it++) {
            int slot = tid + it * 256;
            int row = slot >> 5;
            int c4 = slot & 31;
            float4 v = ((const float4*)(g_ctx + row * S_ + kt))[c4];
            *(float4*)&sctx[row][c4 * 4] = v;
        }
        // sW tile: 128 rows x 32 cols = 1024 float4, 4 per thread
#pragma unroll
        for (int it = 0; it < 4; it++) {
            int slot = tid + it * 256;
            int k = slot >> 3;
            int c4 = slot & 7;
            float4 v = *(const float4*)(Wb + (size_t)(kt + k) * D_ + chunk + c4 * 4);
            *(float4*)&sW[k][c4 * 4] = v;
        }
        __syncthreads();
#pragma unroll 4
        for (int k = 0; k < CKT; k++) {
            float cv = sctx[b][k];
            float4 w = *(const float4*)&sW[k][dgrp * 4];
            acc[0] += cv * w.x;
            acc[1] += cv * w.y;
            acc[2] += cv * w.z;
            acc[3] += cv * w.w;
        }
        __syncthreads();
    }

    float4 bias = *(const float4*)(b3 + d);
    float4 o;
    o.x = acc[0] + bias.x;
    o.y = acc[1] + bias.y;
    o.z = acc[2] + bias.z;
    o.w = acc[3] + bias.w;
    *(float4*)(g_c + b * D_ + d) = o;
}

// ---------------------------------------------------------------------------
// Kernel 5: out[m,n] = sum_k x[m,k] * W3top[k,n] + c[m>>5, n]
// M=1024, N=512, K=512. BM=32, BN=64, BK=32, 128 threads, 4x4 microtile.
// grid (8, 32) = 256 CTAs. Inner product uses packed fma.rn.f32x2.
// ---------------------------------------------------------------------------
#define OBM 32
#define OBN 64
#define OBK 32

__global__ __launch_bounds__(128) void out_gemm(const float* __restrict__ A,
                                                const float* __restrict__ W3,
                                                float* __restrict__ out) {
    __shared__ float As[OBK][OBM + 4];
    __shared__ float Bs[OBK][OBN + 4];

    int tid = threadIdx.x;
    int tx = tid & 15;    // n-sub: tx*4
    int ty = tid >> 4;    // m-sub: ty*4 (0..7)
    int m0 = blockIdx.y * OBM, n0 = blockIdx.x * OBN;

    unsigned long long acc[4][2];
#pragma unroll
    for (int i = 0; i < 4; i++) {
        acc[i][0] = 0ull;
        acc[i][1] = 0ull;
    }

    for (int k0 = 0; k0 < D_; k0 += OBK) {
        // A tile: 32 m-rows x 8 float4 = 256 slots, 2 per thread; store transposed
#pragma unroll
        for (int it = 0; it < 2; it++) {
            int slot = tid + it * 128;
            int m = slot >> 3;
            int k4 = slot & 7;
            float4 v = *(const float4*)(A + (size_t)(m0 + m) * D_ + k0 + k4 * 4);
            As[k4 * 4 + 0][m] = v.x;
            As[k4 * 4 + 1][m] = v.y;
            As[k4 * 4 + 2][m] = v.z;
            As[k4 * 4 + 3][m] = v.w;
        }
        // B tile: 32 k-rows x 16 float4 = 512 slots, 4 per thread
#pragma unroll
        for (int it = 0; it < 4; it++) {
            int slot = tid + it * 128;
            int k = slot >> 4;
            int n4 = slot & 15;
            float4 v = *(const float4*)(W3 + (size_t)(k0 + k) * D_ + n0 + n4 * 4);
            *(float4*)&Bs[k][n4 * 4] = v;
        }
        __syncthreads();

#pragma unroll
        for (int k = 0; k < OBK; k++) {
            float4 a4 = *(const float4*)&As[k][ty * 4];
            float4 b4 = *(const float4*)&Bs[k][tx * 4];
            unsigned long long bb0 = pack2(b4.x, b4.y);
            unsigned long long bb1 = pack2(b4.z, b4.w);
            unsigned long long aa;
            aa = pack2(a4.x, a4.x);
            fma2(acc[0][0], aa, bb0);
            fma2(acc[0][1], aa, bb1);
            aa = pack2(a4.y, a4.y);
            fma2(acc[1][0], aa, bb0);
            fma2(acc[1][1], aa, bb1);
            aa = pack2(a4.z, a4.z);
            fma2(acc[2][0], aa, bb0);
            fma2(acc[2][1], aa, bb1);
            aa = pack2(a4.w, a4.w);
            fma2(acc[3][0], aa, bb0);
            fma2(acc[3][1], aa, bb1);
        }
        __syncthreads();
    }

    // batch index is constant per CTA: m0 = blockIdx.y*32, T=32 => b = blockIdx.y
    const float* crow = g_c + blockIdx.y * D_;
#pragma unroll
    for (int i = 0; i < 4; i++) {
        int m = m0 + ty * 4 + i;
        int n = n0 + tx * 4;
        float2 p0 = unpack2(acc[i][0]);
        float2 p1 = unpack2(acc[i][1]);
        float4 cv = *(const float4*)(crow + n);
        float4 ov;
        ov.x = p0.x + cv.x;
        ov.y = p0.y + cv.y;
        ov.z = p1.x + cv.z;
        ov.w = p1.y + cv.w;
        *(float4*)(out + (size_t)m * D_ + n) = ov;
    }
}

extern "C" void kernel_launch(void* const* d_in, const int* in_sizes, int n_in,
                              void* d_out, int out_size) {
    const float* x  = (const float*)d_in[0];   // [32,32,512]
    const float* xs = (const float*)d_in[1];   // [32,196,512]
    const float* W1 = (const float*)d_in[3];   // [512,512]
    const float* W3 = (const float*)d_in[5];   // [1024,512]
    const float* b3 = (const float*)d_in[7];   // [512]
    const float* V  = (const float*)d_in[8];   // [512,1]
    float* out = (float*)d_out;                // [32,32,512]

    w1v_kernel<<<64, 256>>>(W1, V);
    scores_kernel<<<dim3(7, B_), 256>>>(xs);
    ctx_kernel<<<dim3(4, B_), 128>>>(xs);
    c_gemm<<<16, 256>>>(W3, b3);
    out_gemm<<<dim3(D_ / OBN, (B_ * T_) / OBM), 128>>>(x, W3, out);
}

// round 5
// speedup vs baseline: 2.7423x; 1.2172x over previous
#include <cuda_runtime.h>
#include <cuda_bf16.h>

// Problem: B=32, T=32, L=196, S=512, D=512
// Math reduction: softmax is shift-invariant => attention independent of h,t.
//   attn[b,:]  = softmax_l( x_static[b] @ (W1@V) )
//   ctx[b,:]   = attn[b,:] @ x_static[b]
//   c[b,:]     = ctx[b,:] @ W3[512:,:] + b3   (split-K partials here)
//   out[b,t,:] = x[b,t,:] @ W3[:512,:] + c[b,:]

#define D_ 512
#define S_ 512
#define L_ 196
#define B_ 32
#define T_ 32
#define NSPLIT 4

__device__ float g_w1v[S_];
__device__ float g_scores[B_ * L_];
__device__ float g_ctx[B_ * S_];
__device__ float g_cpart[NSPLIT][B_][D_];

// ---- packed fp32x2 helpers (Blackwell FFMA2, PTX-only) ----------------------
__device__ __forceinline__ unsigned long long pack2(float lo, float hi) {
    unsigned long long r;
    asm("mov.b64 %0, {%1, %2};" : "=l"(r) : "f"(lo), "f"(hi));
    return r;
}
__device__ __forceinline__ void fma2(unsigned long long& d, unsigned long long a,
                                     unsigned long long b) {
    asm("fma.rn.f32x2 %0, %1, %2, %0;" : "+l"(d) : "l"(a), "l"(b));
}
__device__ __forceinline__ float2 unpack2(unsigned long long p) {
    float2 f;
    asm("mov.b64 {%0, %1}, %2;" : "=f"(f.x), "=f"(f.y) : "l"(p));
    return f;
}

// ---------------------------------------------------------------------------
// Kernel 1: w1v[s] = dot(W1[s,:], V). warp per row, float4.
// ---------------------------------------------------------------------------
__global__ __launch_bounds__(256) void w1v_kernel(const float* __restrict__ W1,
                                                  const float* __restrict__ V) {
    int gwarp = (blockIdx.x * blockDim.x + threadIdx.x) >> 5;
    int lane = threadIdx.x & 31;
    if (gwarp >= S_) return;
    const float4* row = (const float4*)(W1 + (size_t)gwarp * D_);
    const float4* v4 = (const float4*)V;
    float acc = 0.0f;
#pragma unroll
    for (int i = 0; i < 4; i++) {
        int idx = lane + i * 32;
        float4 a = row[idx];
        float4 b = v4[idx];
        acc += a.x * b.x + a.y * b.y + a.z * b.z + a.w * b.w;
    }
#pragma unroll
    for (int o = 16; o; o >>= 1) acc += __shfl_xor_sync(0xffffffffu, acc, o);
    if (lane == 0) g_w1v[gwarp] = acc;
}

// ---------------------------------------------------------------------------
// Kernel 2: scores[b,l] = dot(x_static[b,l,:], w1v). grid (7, 32), warp/row.
// ---------------------------------------------------------------------------
__global__ __launch_bounds__(256) void scores_kernel(const float* __restrict__ xs) {
    int b = blockIdx.y;
    int l0 = blockIdx.x * 28;
    __shared__ float sw1v[S_];
    int tid = threadIdx.x;
    if (tid < S_ / 4) ((float4*)sw1v)[tid] = ((const float4*)g_w1v)[tid];
    __syncthreads();

    int warp = tid >> 5, lane = tid & 31;
    const float* X = xs + (size_t)b * L_ * S_;
    for (int r = warp; r < 28; r += 8) {
        int l = l0 + r;
        const float4* row = (const float4*)(X + (size_t)l * S_);
        const float4* w4 = (const float4*)sw1v;
        float acc = 0.0f;
#pragma unroll
        for (int i = 0; i < 4; i++) {
            int idx = lane + i * 32;
            float4 a = row[idx];
            float4 w = w4[idx];
            acc += a.x * w.x + a.y * w.y + a.z * w.z + a.w * w.w;
        }
#pragma unroll
        for (int o = 16; o; o >>= 1) acc += __shfl_xor_sync(0xffffffffu, acc, o);
        if (lane == 0) g_scores[b * L_ + l] = acc;
    }
}

// ---------------------------------------------------------------------------
// Kernel 3: softmax (recomputed per block) + ctx.
// grid (4, 32): s-chunk of 128, batch b. block 128.
// ---------------------------------------------------------------------------
__global__ __launch_bounds__(128) void ctx_kernel(const float* __restrict__ xs) {
    int b = blockIdx.y;
    int s = blockIdx.x * 128 + threadIdx.x;
    __shared__ float sc[L_];
    __shared__ float red[4];
    __shared__ float s_max, s_sum;
    int tid = threadIdx.x;
    int warp = tid >> 5, lane = tid & 31;

    float v0 = g_scores[b * L_ + tid];
    float v1 = (tid + 128 < L_) ? g_scores[b * L_ + tid + 128] : -1e30f;

    float m = fmaxf(v0, v1);
#pragma unroll
    for (int o = 16; o; o >>= 1) m = fmaxf(m, __shfl_xor_sync(0xffffffffu, m, o));
    if (lane == 0) red[warp] = m;
    __syncthreads();
    if (tid == 0) s_max = fmaxf(fmaxf(red[0], red[1]), fmaxf(red[2], red[3]));
    __syncthreads();
    float mx = s_max;

    float e0 = __expf(v0 - mx);
    float e1 = (tid + 128 < L_) ? __expf(v1 - mx) : 0.0f;
    float ps = e0 + e1;
#pragma unroll
    for (int o = 16; o; o >>= 1) ps += __shfl_xor_sync(0xffffffffu, ps, o);
    if (lane == 0) red[warp] = ps;
    __syncthreads();
    if (tid == 0) s_sum = red[0] + red[1] + red[2] + red[3];
    __syncthreads();
    float inv = 1.0f / s_sum;
    sc[tid] = e0 * inv;
    if (tid + 128 < L_) sc[tid + 128] = e1 * inv;
    __syncthreads();

    const float* Xp = xs + (size_t)b * L_ * S_ + s;
    float acc = 0.0f;
#pragma unroll 4
    for (int l = 0; l < L_; l++) acc += sc[l] * Xp[(size_t)l * S_];
    g_ctx[b * S_ + s] = acc;
}

// ---------------------------------------------------------------------------
// Kernel 4: split-K partials of c: g_cpart[split][b][d] =
//   sum_{k in split} ctx[b,k] * W3bot[k,d]
// grid (32 d-chunks of 16, 4 k-splits of 128). block 128:
//   thread = (b = tid>>2, d4 = tid&3). Single tile, no kt loop.
// ---------------------------------------------------------------------------
#define CKT 128
__global__ __launch_bounds__(128) void c_gemm_split(const float* __restrict__ W3) {
    __shared__ float sctx[B_][CKT + 4];
    __shared__ float sW[CKT][16];
    const float* Wb = W3 + (size_t)S_ * D_;
    int tid = threadIdx.x;
    int chunk = blockIdx.x * 16;
    int split = blockIdx.y;
    int k0 = split * CKT;

    // load ctx tile [32][128]: 1024 float4, 8 per thread
#pragma unroll
    for (int it = 0; it < 8; it++) {
        int slot = tid + it * 128;
        int row = slot >> 5;
        int c4 = slot & 31;
        float4 v = ((const float4*)(g_ctx + row * S_ + k0))[c4];
        *(float4*)&sctx[row][c4 * 4] = v;
    }
    // load W tile [128][16]: 512 float4, 4 per thread
#pragma unroll
    for (int it = 0; it < 4; it++) {
        int slot = tid + it * 128;
        int k = slot >> 2;
        int c4 = slot & 3;
        float4 v = *(const float4*)(Wb + (size_t)(k0 + k) * D_ + chunk + c4 * 4);
        *(float4*)&sW[k][c4 * 4] = v;
    }
    __syncthreads();

    int b = tid >> 2;
    int d4 = tid & 3;
    float acc[4] = {0.0f, 0.0f, 0.0f, 0.0f};
#pragma unroll 8
    for (int k = 0; k < CKT; k++) {
        float cv = sctx[b][k];
        float4 w = *(const float4*)&sW[k][d4 * 4];
        acc[0] += cv * w.x;
        acc[1] += cv * w.y;
        acc[2] += cv * w.z;
        acc[3] += cv * w.w;
    }
    *(float4*)&g_cpart[split][b][chunk + d4 * 4] = *(float4*)acc;
}

// ---------------------------------------------------------------------------
// Kernel 5: out[m,n] = sum_k x[m,k] * W3top[k,n] + b3[n] + sum_s cpart[s][b][n]
// M=1024, N=512, K=512. BM=32, BN=64, BK=32, 128 threads, 4x4 microtile.
// grid (8, 32) = 256 CTAs. Inner product uses packed fma.rn.f32x2.
// ---------------------------------------------------------------------------
#define OBM 32
#define OBN 64
#define OBK 32

__global__ __launch_bounds__(128) void out_gemm(const float* __restrict__ A,
                                                const float* __restrict__ W3,
                                                const float* __restrict__ b3,
                                                float* __restrict__ out) {
    __shared__ float As[OBK][OBM + 4];
    __shared__ float Bs[OBK][OBN + 4];

    int tid = threadIdx.x;
    int tx = tid & 15;
    int ty = tid >> 4;
    int m0 = blockIdx.y * OBM, n0 = blockIdx.x * OBN;

    unsigned long long acc[4][2];
#pragma unroll
    for (int i = 0; i < 4; i++) {
        acc[i][0] = 0ull;
        acc[i][1] = 0ull;
    }

    for (int k0 = 0; k0 < D_; k0 += OBK) {
#pragma unroll
        for (int it = 0; it < 2; it++) {
            int slot = tid + it * 128;
            int m = slot >> 3;
            int k4 = slot & 7;
            float4 v = *(const float4*)(A + (size_t)(m0 + m) * D_ + k0 + k4 * 4);
            As[k4 * 4 + 0][m] = v.x;
            As[k4 * 4 + 1][m] = v.y;
            As[k4 * 4 + 2][m] = v.z;
            As[k4 * 4 + 3][m] = v.w;
        }
#pragma unroll
        for (int it = 0; it < 4; it++) {
            int slot = tid + it * 128;
            int k = slot >> 4;
            int n4 = slot & 15;
            float4 v = *(const float4*)(W3 + (size_t)(k0 + k) * D_ + n0 + n4 * 4);
            *(float4*)&Bs[k][n4 * 4] = v;
        }
        __syncthreads();

#pragma unroll
        for (int k = 0; k < OBK; k++) {
            float4 a4 = *(const float4*)&As[k][ty * 4];
            float4 b4 = *(const float4*)&Bs[k][tx * 4];
            unsigned long long bb0 = pack2(b4.x, b4.y);
            unsigned long long bb1 = pack2(b4.z, b4.w);
            unsigned long long aa;
            aa = pack2(a4.x, a4.x);
            fma2(acc[0][0], aa, bb0);
            fma2(acc[0][1], aa, bb1);
            aa = pack2(a4.y, a4.y);
            fma2(acc[1][0], aa, bb0);
            fma2(acc[1][1], aa, bb1);
            aa = pack2(a4.z, a4.z);
            fma2(acc[2][0], aa, bb0);
            fma2(acc[2][1], aa, bb1);
            aa = pack2(a4.w, a4.w);
            fma2(acc[3][0], aa, bb0);
            fma2(acc[3][1], aa, bb1);
        }
        __syncthreads();
    }

    // c[b][n] = b3[n] + sum_s cpart[s][b][n]; b = blockIdx.y (OBM == T_)
    int b = blockIdx.y;
    int n = n0 + tx * 4;
    float4 cv = *(const float4*)(b3 + n);
#pragma unroll
    for (int s = 0; s < NSPLIT; s++) {
        float4 p = *(const float4*)&g_cpart[s][b][n];
        cv.x += p.x;
        cv.y += p.y;
        cv.z += p.z;
        cv.w += p.w;
    }

#pragma unroll
    for (int i = 0; i < 4; i++) {
        int m = m0 + ty * 4 + i;
        float2 p0 = unpack2(acc[i][0]);
        float2 p1 = unpack2(acc[i][1]);
        float4 ov;
        ov.x = p0.x + cv.x;
        ov.y = p0.y + cv.y;
        ov.z = p1.x + cv.z;
        ov.w = p1.y + cv.w;
        *(float4*)(out + (size_t)m * D_ + n) = ov;
    }
}

extern "C" void kernel_launch(void* const* d_in, const int* in_sizes, int n_in,
                              void* d_out, int out_size) {
    const float* x  = (const float*)d_in[0];   // [32,32,512]
    const float* xs = (const float*)d_in[1];   // [32,196,512]
    const float* W1 = (const float*)d_in[3];   // [512,512]
    const float* W3 = (const float*)d_in[5];   // [1024,512]
    const float* b3 = (const float*)d_in[7];   // [512]
    const float* V  = (const float*)d_in[8];   // [512,1]
    float* out = (float*)d_out;                // [32,32,512]

    w1v_kernel<<<64, 256>>>(W1, V);
    scores_kernel<<<dim3(7, B_), 256>>>(xs);
    ctx_kernel<<<dim3(4, B_), 128>>>(xs);
    c_gemm_split<<<dim3(32, NSPLIT), 128>>>(W3);
    out_gemm<<<dim3(D_ / OBN, (B_ * T_) / OBM), 128>>>(x, W3, b3, out);
}